// round 6
// baseline (speedup 1.0000x reference)
#include <cuda_runtime.h>
#include <cuda_bf16.h>
#include <cstddef>

#define N_MODELS 63

// HBM-bound streaming kernel. 504 MB mandatory reads, zero reuse:
//  - int4 loads (4 samples/thread/row), fully coalesced 128B warp transactions
//  - __ldcs streaming hint on the votes stream (evict-first: no point caching
//    a once-read 504MB stream in L1/L2), __stcs on the 8MB output
//  - __launch_bounds__(256, 6) nudges regs <=42 -> 6 blocks/SM (occ ~75%)
//  - c1/c0 accumulated SEPARATELY, sequentially over m, to exactly mirror the
//    reference's two-sum-then-compare fp semantics (rel_err must stay 0.0:
//    a single flipped marginal sample = 1e-3 rel_err = fail)
__global__ __launch_bounds__(256, 6)
void vote4_kernel(const int4* __restrict__ votes,
                  const float* __restrict__ weights,
                  float4* __restrict__ out,
                  int n4) {
    __shared__ float sw[N_MODELS];
    if (threadIdx.x < N_MODELS) sw[threadIdx.x] = weights[threadIdx.x];
    __syncthreads();

    int i = blockIdx.x * blockDim.x + threadIdx.x;
    int stride = gridDim.x * blockDim.x;

    for (; i < n4; i += stride) {
        float c1x = 0.f, c1y = 0.f, c1z = 0.f, c1w = 0.f;
        float c0x = 0.f, c0y = 0.f, c0z = 0.f, c0w = 0.f;
        const int4* p = votes + i;
#pragma unroll
        for (int m = 0; m < N_MODELS; m++) {
            int4 v = __ldcs(p);
            p += n4;
            float wm = sw[m];
            // +0.0f adds are exact: preserves the reference's per-branch sums.
            c1x += v.x ? wm : 0.0f;  c0x += v.x ? 0.0f : wm;
            c1y += v.y ? wm : 0.0f;  c0y += v.y ? 0.0f : wm;
            c1z += v.z ? wm : 0.0f;  c0z += v.z ? 0.0f : wm;
            c1w += v.w ? wm : 0.0f;  c0w += v.w ? 0.0f : wm;
        }
        float4 o;
        o.x = (c1x > c0x) ? 1.0f : 0.0f;
        o.y = (c1y > c0y) ? 1.0f : 0.0f;
        o.z = (c1z > c0z) ? 1.0f : 0.0f;
        o.w = (c1w > c0w) ? 1.0f : 0.0f;
        __stcs(&out[i], o);
    }
}

// Scalar tail (never runs for n = 2e6, kept for generality).
__global__ void vote_tail_kernel(const int* __restrict__ votes,
                                 const float* __restrict__ weights,
                                 float* __restrict__ out,
                                 int n, int start) {
    int i = start + blockIdx.x * blockDim.x + threadIdx.x;
    if (i >= n) return;
    float c1 = 0.f, c0 = 0.f;
    for (int m = 0; m < N_MODELS; m++) {
        float wm = weights[m];
        if (votes[(size_t)m * (size_t)n + (size_t)i]) c1 += wm; else c0 += wm;
    }
    out[i] = (c1 > c0) ? 1.0f : 0.0f;
}

extern "C" void kernel_launch(void* const* d_in, const int* in_sizes, int n_in,
                              void* d_out, int out_size) {
    // Bind inputs by SIZE: weights has exactly N_MODELS elements.
    const int* votes = nullptr;
    const float* weights = nullptr;
    long long votes_elems = 0;
    for (int k = 0; k < n_in; k++) {
        if (in_sizes[k] == N_MODELS) {
            weights = (const float*)d_in[k];
        } else {
            votes = (const int*)d_in[k];
            votes_elems = in_sizes[k];
        }
    }
    float* out = (float*)d_out;   // float32 0/1 (established round 4)

    int n = (int)(votes_elems / N_MODELS);   // samples (2e6)
    int n4 = n / 4;
    int tail_start = n4 * 4;

    if (n4 > 0) {
        const int threads = 256;
        int blocks = (n4 + threads - 1) / threads;
        vote4_kernel<<<blocks, threads>>>((const int4*)votes, weights,
                                          (float4*)out, n4);
    }
    if (tail_start < n) {
        int rem = n - tail_start;
        vote_tail_kernel<<<(rem + 127) / 128, 128>>>(votes, weights, out, n,
                                                     tail_start);
    }
}